// round 6
// baseline (speedup 1.0000x reference)
#include <cuda_runtime.h>
#include <math.h>

#define HALF_DIM 128
#define DIM 256
#define ROWS_PER_TASK 8
#define GRID_CTAS 1184          // ~148 SMs x 8 resident CTAs: single-wave persistent grid
#define BLOCK_THREADS 256

// ---------------------------------------------------------------------------
// Compile-time inv_freq table: inv_freq_i = 10000^(-i/128) = exp(-i*ln(1e4)/128)
// computed in constexpr double precision (range-reduced Taylor), cast to float.
// ---------------------------------------------------------------------------
constexpr double CEXP_LN2 = 0.6931471805599453;

constexpr double cexp(double x) {
    int n = (int)(x / CEXP_LN2 + (x >= 0.0 ? 0.5 : -0.5));
    double r = x - (double)n * CEXP_LN2;   // |r| <= ln2/2
    double term = 1.0, sum = 1.0;
    for (int k = 1; k < 26; k++) {
        term *= r / (double)k;
        sum += term;
    }
    double p = 1.0;
    if (n >= 0) { for (int i = 0; i < n;  i++) p *= 2.0; }
    else        { for (int i = 0; i < -n; i++) p *= 0.5; }
    return sum * p;
}

struct FreqTable { float v[HALF_DIM]; };

constexpr FreqTable make_table() {
    FreqTable t{};
    for (int i = 0; i < HALF_DIM; i++) {
        t.v[i] = (float)cexp(-(double)i * (9.210340371976184 / 128.0));
    }
    return t;
}

__device__ const FreqTable g_tab = make_table();

// Lane j owns freqs {2j, 2j+1, 64+2j, 64+2j+1} so that the two float4
// stores per row are WARP-CONTIGUOUS 512-byte segments (full-sector,
// full-line writes -> no DRAM read-modify-write).
__device__ __forceinline__ void compute_row(float xb, const float fr[4],
                                            float* __restrict__ out_row, int lane) {
    const float INV_2PI = 0.15915494309189535f;
    const float C1 = 6.2831854820251465f;      // fp32(2*pi)
    const float C2 = -1.7484555e-7f;           // 2*pi - C1

    float res[8];
#pragma unroll
    for (int t = 0; t < 4; t++) {
        float emb = xb * fr[t];
        float k = rintf(emb * INV_2PI);
        float r = fmaf(-k, C1, emb);
        r = fmaf(-k, C2, r);                   // |r| <= pi
        float s, c;
        __sincosf(r, &s, &c);                  // MUFU.SIN / MUFU.COS
        res[2 * t]     = s;
        res[2 * t + 1] = c;
    }

    float4* seg0 = reinterpret_cast<float4*>(out_row) + lane;
    float4* seg1 = reinterpret_cast<float4*>(out_row + 128) + lane;
    __stcs(seg0, make_float4(res[0], res[1], res[2], res[3]));  // streaming store
    __stcs(seg1, make_float4(res[4], res[5], res[6], res[7]));
}

__global__ __launch_bounds__(BLOCK_THREADS, 8)
void sinusoidal_kernel(const float* __restrict__ x,
                       float* __restrict__ out,
                       int n_rows) {
    const int lane = threadIdx.x & 31;
    const int warp_in_cta = threadIdx.x >> 5;
    const int warps_per_cta = BLOCK_THREADS >> 5;
    const long long total_warps = (long long)gridDim.x * warps_per_cta;
    const long long n_tasks = ((long long)n_rows + ROWS_PER_TASK - 1) / ROWS_PER_TASK;

    // Per-warp-resident frequency registers (loaded once per warp)
    float2 fa = *reinterpret_cast<const float2*>(g_tab.v + 2 * lane);
    float2 fb = *reinterpret_cast<const float2*>(g_tab.v + 64 + 2 * lane);
    float fr[4] = { fa.x, fa.y, fb.x, fb.y };

    long long task = (long long)blockIdx.x * warps_per_cta + warp_in_cta;
    for (; task < n_tasks; task += total_warps) {
        const int row_base = (int)(task * ROWS_PER_TASK);
        const int nrows = min(ROWS_PER_TASK, n_rows - row_base);

        float xv = (lane < nrows) ? x[row_base + lane] : 0.0f;
        float* orow = out + (size_t)row_base * DIM;

        if (nrows == ROWS_PER_TASK) {
#pragma unroll
            for (int t = 0; t < ROWS_PER_TASK; t++) {
                float xb = __shfl_sync(0xffffffffu, xv, t);
                compute_row(xb, fr, orow, lane);
                orow += DIM;
            }
        } else {
            for (int t = 0; t < nrows; t++) {
                float xb = __shfl_sync(0xffffffffu, xv, t);
                compute_row(xb, fr, orow, lane);
                orow += DIM;
            }
        }
    }
}

extern "C" void kernel_launch(void* const* d_in, const int* in_sizes, int n_in,
                              void* d_out, int out_size) {
    const float* x = (const float*)d_in[0];
    float* out = (float*)d_out;
    int n_rows = in_sizes[0];          // 1048576

    sinusoidal_kernel<<<GRID_CTAS, BLOCK_THREADS>>>(x, out, n_rows);
}

// round 7
// speedup vs baseline: 1.2299x; 1.2299x over previous
#include <cuda_runtime.h>
#include <math.h>

#define HALF_DIM 128
#define DIM 256
#define ROWS_PER_WARP 4
#define BLOCK_THREADS 256

// ---------------------------------------------------------------------------
// Compile-time inv_freq table: inv_freq_i = 10000^(-i/128) = exp(-i*ln(1e4)/128)
// computed in constexpr double precision (range-reduced Taylor), cast to float.
// ---------------------------------------------------------------------------
constexpr double CEXP_LN2 = 0.6931471805599453;

constexpr double cexp(double x) {
    int n = (int)(x / CEXP_LN2 + (x >= 0.0 ? 0.5 : -0.5));
    double r = x - (double)n * CEXP_LN2;   // |r| <= ln2/2
    double term = 1.0, sum = 1.0;
    for (int k = 1; k < 26; k++) {
        term *= r / (double)k;
        sum += term;
    }
    double p = 1.0;
    if (n >= 0) { for (int i = 0; i < n;  i++) p *= 2.0; }
    else        { for (int i = 0; i < -n; i++) p *= 0.5; }
    return sum * p;
}

struct FreqTable { float v[HALF_DIM]; };

constexpr FreqTable make_table() {
    FreqTable t{};
    for (int i = 0; i < HALF_DIM; i++) {
        t.v[i] = (float)cexp(-(double)i * (9.210340371976184 / 128.0));
    }
    return t;
}

__device__ const FreqTable g_tab = make_table();

// Lane j owns freqs {2j, 2j+1, 64+2j, 64+2j+1} so that the two float4
// stores per row are WARP-CONTIGUOUS 512-byte segments (full-sector,
// full-line writes -> no DRAM read-modify-write).
__device__ __forceinline__ void compute_row(float xb, const float fr[4],
                                            float* __restrict__ out_row, int lane) {
    const float INV_2PI = 0.15915494309189535f;
    const float C1 = 6.2831854820251465f;      // fp32(2*pi)
    const float C2 = -1.7484555e-7f;           // 2*pi - C1

    float res[8];
#pragma unroll
    for (int t = 0; t < 4; t++) {
        float emb = xb * fr[t];
        float k = rintf(emb * INV_2PI);
        float r = fmaf(-k, C1, emb);
        r = fmaf(-k, C2, r);                   // |r| <= pi
        float s, c;
        __sincosf(r, &s, &c);                  // MUFU.SIN / MUFU.COS
        res[2 * t]     = s;
        res[2 * t + 1] = c;
    }

    float4* seg0 = reinterpret_cast<float4*>(out_row) + lane;
    float4* seg1 = reinterpret_cast<float4*>(out_row + 128) + lane;
    __stcs(seg0, make_float4(res[0], res[1], res[2], res[3]));  // streaming store
    __stcs(seg1, make_float4(res[4], res[5], res[6], res[7]));
}

__global__ __launch_bounds__(BLOCK_THREADS, 8)
void sinusoidal_kernel(const float* __restrict__ x,
                       float* __restrict__ out,
                       int n_rows) {
    const int lane = threadIdx.x & 31;
    const int warp_global = (blockIdx.x * BLOCK_THREADS + threadIdx.x) >> 5;
    const int row_base = warp_global * ROWS_PER_WARP;
    if (row_base >= n_rows) return;

    // Per-warp-resident frequency registers (loaded once per warp)
    float2 fa = *reinterpret_cast<const float2*>(g_tab.v + 2 * lane);
    float2 fb = *reinterpret_cast<const float2*>(g_tab.v + 64 + 2 * lane);
    float fr[4] = { fa.x, fa.y, fb.x, fb.y };

    const int nrows = min(ROWS_PER_WARP, n_rows - row_base);

    // One coalesced load covers this warp's x values
    float xv = (lane < nrows) ? x[row_base + lane] : 0.0f;
    float* orow = out + (size_t)row_base * DIM;

    if (nrows == ROWS_PER_WARP) {
#pragma unroll
        for (int t = 0; t < ROWS_PER_WARP; t++) {
            float xb = __shfl_sync(0xffffffffu, xv, t);
            compute_row(xb, fr, orow, lane);
            orow += DIM;
        }
    } else {
        for (int t = 0; t < nrows; t++) {
            float xb = __shfl_sync(0xffffffffu, xv, t);
            compute_row(xb, fr, orow, lane);
            orow += DIM;
        }
    }
}

extern "C" void kernel_launch(void* const* d_in, const int* in_sizes, int n_in,
                              void* d_out, int out_size) {
    const float* x = (const float*)d_in[0];
    float* out = (float*)d_out;
    int n_rows = in_sizes[0];          // 1048576

    long long n_warps = ((long long)n_rows + ROWS_PER_WARP - 1) / ROWS_PER_WARP;
    long long total_threads = n_warps * 32;
    int grid = (int)((total_threads + BLOCK_THREADS - 1) / BLOCK_THREADS);
    sinusoidal_kernel<<<grid, BLOCK_THREADS>>>(x, out, n_rows);
}

// round 9
// speedup vs baseline: 1.2463x; 1.0133x over previous
#include <cuda_runtime.h>
#include <math.h>

#define HALF_DIM 128
#define DIM 256
#define ROWS_PER_WARP 2
#define BLOCK_THREADS 256

// ---------------------------------------------------------------------------
// Compile-time inv_freq table: inv_freq_i = 10000^(-i/128) = exp(-i*ln(1e4)/128)
// computed in constexpr double precision (range-reduced Taylor), cast to float.
// ---------------------------------------------------------------------------
constexpr double CEXP_LN2 = 0.6931471805599453;

constexpr double cexp(double x) {
    int n = (int)(x / CEXP_LN2 + (x >= 0.0 ? 0.5 : -0.5));
    double r = x - (double)n * CEXP_LN2;   // |r| <= ln2/2
    double term = 1.0, sum = 1.0;
    for (int k = 1; k < 26; k++) {
        term *= r / (double)k;
        sum += term;
    }
    double p = 1.0;
    if (n >= 0) { for (int i = 0; i < n;  i++) p *= 2.0; }
    else        { for (int i = 0; i < -n; i++) p *= 0.5; }
    return sum * p;
}

struct FreqTable { float v[HALF_DIM]; };

constexpr FreqTable make_table() {
    FreqTable t{};
    for (int i = 0; i < HALF_DIM; i++) {
        t.v[i] = (float)cexp(-(double)i * (9.210340371976184 / 128.0));
    }
    return t;
}

__device__ const FreqTable g_tab = make_table();

// Lane j owns freqs {2j, 2j+1, 64+2j, 64+2j+1} so that the two float4
// stores per row are WARP-CONTIGUOUS 512-byte segments (full-sector,
// full-line writes -> no DRAM read-modify-write).
__device__ __forceinline__ void compute_row(float xb, const float fr[4],
                                            float* __restrict__ out_row, int lane) {
    const float INV_2PI = 0.15915494309189535f;
    const float C1 = 6.2831854820251465f;      // fp32(2*pi)
    const float C2 = -1.7484555e-7f;           // 2*pi - C1

    float res[8];
#pragma unroll
    for (int t = 0; t < 4; t++) {
        float emb = xb * fr[t];
        float k = rintf(emb * INV_2PI);
        float r = fmaf(-k, C1, emb);
        r = fmaf(-k, C2, r);                   // |r| <= pi
        float s, c;
        __sincosf(r, &s, &c);                  // MUFU.SIN / MUFU.COS
        res[2 * t]     = s;
        res[2 * t + 1] = c;
    }

    float4* seg0 = reinterpret_cast<float4*>(out_row) + lane;
    float4* seg1 = reinterpret_cast<float4*>(out_row + 128) + lane;
    __stcs(seg0, make_float4(res[0], res[1], res[2], res[3]));  // streaming store
    __stcs(seg1, make_float4(res[4], res[5], res[6], res[7]));
}

__global__ __launch_bounds__(BLOCK_THREADS, 8)
void sinusoidal_kernel(const float* __restrict__ x,
                       float* __restrict__ out,
                       int n_rows) {
    const int lane = threadIdx.x & 31;
    const int warp_global = (blockIdx.x * BLOCK_THREADS + threadIdx.x) >> 5;
    const int row_base = warp_global * ROWS_PER_WARP;
    if (row_base >= n_rows) return;

    // Per-warp-resident frequency registers (loaded once per warp)
    float2 fa = *reinterpret_cast<const float2*>(g_tab.v + 2 * lane);
    float2 fb = *reinterpret_cast<const float2*>(g_tab.v + 64 + 2 * lane);
    float fr[4] = { fa.x, fa.y, fb.x, fb.y };

    const int nrows = min(ROWS_PER_WARP, n_rows - row_base);

    // One coalesced load covers this warp's x values
    float xv = (lane < nrows) ? x[row_base + lane] : 0.0f;
    float* orow = out + (size_t)row_base * DIM;

    if (nrows == ROWS_PER_WARP) {
#pragma unroll
        for (int t = 0; t < ROWS_PER_WARP; t++) {
            float xb = __shfl_sync(0xffffffffu, xv, t);
            compute_row(xb, fr, orow, lane);
            orow += DIM;
        }
    } else {
        for (int t = 0; t < nrows; t++) {
            float xb = __shfl_sync(0xffffffffu, xv, t);
            compute_row(xb, fr, orow, lane);
            orow += DIM;
        }
    }
}

extern "C" void kernel_launch(void* const* d_in, const int* in_sizes, int n_in,
                              void* d_out, int out_size) {
    const float* x = (const float*)d_in[0];
    float* out = (float*)d_out;
    int n_rows = in_sizes[0];          // 1048576

    long long n_warps = ((long long)n_rows + ROWS_PER_WARP - 1) / ROWS_PER_WARP;
    long long total_threads = n_warps * 32;
    int grid = (int)((total_threads + BLOCK_THREADS - 1) / BLOCK_THREADS);
    sinusoidal_kernel<<<grid, BLOCK_THREADS>>>(x, out, n_rows);
}